// round 10
// baseline (speedup 1.0000x reference)
#include <cuda_runtime.h>
#include <cuda_bf16.h>
#include <cstdint>

#define NN 4096
#define DD 128
#define BB 4096
#define KSPLIT 4
#define KQ (NN / KSPLIT)      // 1024
#define KT (KQ / 32)          // 32 K-iterations of BK=32
#define MAIN_S cudaStreamPerThread

// ---------------- scratch (device globals; no allocation allowed) -------------
__device__ __align__(256) __nv_bfloat16 g_Bh[2][(size_t)DD * NN];  // B^T hi
__device__ __align__(256) __nv_bfloat16 g_Bl[2][(size_t)DD * NN];  // B^T lo
__device__ __align__(256) __nv_bfloat16 g_Wth[4][DD * DD];         // W^T hi
__device__ __align__(256) __nv_bfloat16 g_Wtl[4][DD * DD];         // W^T lo
__device__ __align__(256) float g_Cpart[2 * KSPLIT][(size_t)NN * DD];
__device__ float g_rowsum[2][NN];
__device__ float g_colsum[2][DD];
__device__ float g_pre[2][BB * DD];
__device__ float g_hid[2][BB * DD];

// ---------------- PTX helpers --------------------------------------------------
__device__ __forceinline__ uint32_t s2u(const void* p) {
    return (uint32_t)__cvta_generic_to_shared(p);
}
__device__ __forceinline__ void cp16(uint32_t dst, const void* src) {
    asm volatile("cp.async.cg.shared.global [%0], [%1], 16;" :: "r"(dst), "l"(src));
}
__device__ __forceinline__ void ldsm4(uint32_t& r0, uint32_t& r1, uint32_t& r2,
                                      uint32_t& r3, uint32_t addr) {
    asm volatile("ldmatrix.sync.aligned.m8n8.x4.shared.b16 {%0,%1,%2,%3}, [%4];"
                 : "=r"(r0), "=r"(r1), "=r"(r2), "=r"(r3) : "r"(addr));
}
__device__ __forceinline__ float2 lds64(uint32_t addr) {
    float2 v;
    asm volatile("ld.shared.v2.f32 {%0,%1}, [%2];" : "=f"(v.x), "=f"(v.y) : "r"(addr));
    return v;
}
__device__ __forceinline__ void mma16816(float* c, const uint32_t* a,
                                         uint32_t b0, uint32_t b1) {
    asm volatile(
        "mma.sync.aligned.m16n8k16.row.col.f32.bf16.bf16.f32 "
        "{%0,%1,%2,%3}, {%4,%5,%6,%7}, {%8,%9}, {%0,%1,%2,%3};"
        : "+f"(c[0]), "+f"(c[1]), "+f"(c[2]), "+f"(c[3])
        : "r"(a[0]), "r"(a[1]), "r"(a[2]), "r"(a[3]), "r"(b0), "r"(b1));
}
// 6-instruction split: v -> packed bf16x2 hi + lo
__device__ __forceinline__ void cvt_split(float2 v, uint32_t& h, uint32_t& l) {
    uint32_t hi2;
    asm("cvt.rn.bf16x2.f32 %0, %1, %2;" : "=r"(hi2) : "f"(v.y), "f"(v.x));
    float fx = __uint_as_float(hi2 << 16);
    float fy = __uint_as_float(hi2 & 0xffff0000u);
    float lx = v.x - fx;
    float ly = v.y - fy;
    uint32_t lo2;
    asm("cvt.rn.bf16x2.f32 %0, %1, %2;" : "=r"(lo2) : "f"(ly), "f"(lx));
    h = hi2; l = lo2;
}

// bf16 B tile: 128 rows x 32 bf16 (64B rows), 16B chunk c (0..3), swizzled
__device__ __forceinline__ uint32_t tile_off(int row, int c) {
    return (uint32_t)(row * 64 + ((c ^ ((row >> 1) & 3)) << 4));
}
// fp32 A tile: 128 rows x 32 f32 (128B rows), 16B chunk c (0..7), swizzled
__device__ __forceinline__ uint32_t atile_off(int row, int c) {
    return (uint32_t)(row * 128 + ((c ^ ((row & 3) << 1)) << 4));
}
__device__ __forceinline__ uint32_t atile_addr(int row, int c2) {
    int b = c2 * 4;
    return (uint32_t)(row * 128 + (((b >> 4) ^ ((row & 3) << 1)) << 4) + (b & 15));
}

#define STAGE 32768u          // A f32 16KB | Bh 8KB | Bl 8KB
#define TCG_SMEM (3 * STAGE)  // 96 KB

// ---------------- fragment compute for one resident stage ----------------------
struct Frag { float acc[2][8][4]; };

__device__ __forceinline__ void stage_mma(Frag& F, uint32_t st, int wm0, int wn0, int L) {
    const uint32_t stBh = st + 16384u;
    const uint32_t stBl = st + 24576u;
    #pragma unroll
    for (int ks = 0; ks < 2; ++ks) {
        uint32_t ah[2][4], al[2][4];
        {
            const int r  = wm0 + (L >> 2);
            const int c2 = (L & 3) * 2 + ks * 16;
            #pragma unroll
            for (int mi = 0; mi < 2; ++mi) {
                const int rr = r + mi * 16;
                float2 v00 = lds64(st + atile_addr(rr,     c2));
                float2 v10 = lds64(st + atile_addr(rr + 8, c2));
                float2 v01 = lds64(st + atile_addr(rr,     c2 + 8));
                float2 v11 = lds64(st + atile_addr(rr + 8, c2 + 8));
                cvt_split(v00, ah[mi][0], al[mi][0]);
                cvt_split(v10, ah[mi][1], al[mi][1]);
                cvt_split(v01, ah[mi][2], al[mi][2]);
                cvt_split(v11, ah[mi][3], al[mi][3]);
            }
        }
        const int rb = wn0 + (L & 7) + ((L & 16) >> 1);
        const int hc = (L >> 3) & 1;
        #pragma unroll
        for (int pi = 0; pi < 4; ++pi) {
            uint32_t bh[4], bl[4];
            const uint32_t off = tile_off(rb + pi * 16, ks * 2 + hc);
            ldsm4(bh[0], bh[1], bh[2], bh[3], stBh + off);
            ldsm4(bl[0], bl[1], bl[2], bl[3], stBl + off);
            #pragma unroll
            for (int mi = 0; mi < 2; ++mi) {
                #pragma unroll
                for (int half = 0; half < 2; ++half) {
                    float* c = F.acc[mi][pi * 2 + half];
                    mma16816(c, ah[mi], bh[half * 2], bh[half * 2 + 1]);
                    mma16816(c, ah[mi], bl[half * 2], bl[half * 2 + 1]);
                    mma16816(c, al[mi], bh[half * 2], bh[half * 2 + 1]);
                }
            }
        }
    }
}

// ---------------- merged dual-domain split-precision GEMM (K-split 4) ----------
// grid (32, 2, KSPLIT) = 256 CTAs -> 2 CTAs/SM on most SMs (16 warps: doubles
// warp supply vs the 128-CTA per-domain version whose tensor pipe sat at 49%).
__global__ void __launch_bounds__(256, 2) tc_gemm(
    const float* __restrict__ A0, const float* __restrict__ A1,
    const __nv_bfloat16* __restrict__ Bh0, const __nv_bfloat16* __restrict__ Bh1,
    const __nv_bfloat16* __restrict__ Bl0, const __nv_bfloat16* __restrict__ Bl1,
    float* __restrict__ Cp)
{
    extern __shared__ char smem[];
    const uint32_t sbase = s2u(smem);
    const int tid = threadIdx.x;
    const int dom = blockIdx.y, z = blockIdx.z;
    const int m0 = blockIdx.x * 128;

    const char* sA  = (const char*)(dom ? A1 : A0);
    const char* sBh = (const char*)(dom ? Bh1 : Bh0);
    const char* sBl = (const char*)(dom ? Bl1 : Bl0);

    const int w   = tid >> 5;
    const int L   = tid & 31;
    const int wm0 = (w & 3) * 32;
    const int wn0 = (w >> 2) * 64;

    Frag F;
    #pragma unroll
    for (int i = 0; i < 2; i++)
        #pragma unroll
        for (int j = 0; j < 8; j++)
            #pragma unroll
            for (int q = 0; q < 4; q++) F.acc[i][j][q] = 0.f;

    auto copy_stage = [&](int stage, int kt) {
        const uint32_t st = sbase + (uint32_t)stage * STAGE;
        const size_t kbA = ((size_t)(z * KQ + kt * 32)) * 4;
        #pragma unroll
        for (int q = 0; q < 4; ++q) {
            const int idx = q * 256 + tid;
            const int row = idx >> 3;
            const int c   = idx & 7;
            cp16(st + atile_off(row, c),
                 sA + (((size_t)(m0 + row)) << 14) + kbA + ((size_t)c << 4));
        }
        const size_t kbB = ((size_t)(z * KQ + kt * 32)) * 2;
        #pragma unroll
        for (int q = 0; q < 4; ++q) {
            const int idx  = q * 256 + tid;
            const int tile = idx >> 9;
            const int rem  = idx & 511;
            const int row  = rem >> 2;
            const int c    = rem & 3;
            const char* gp = (tile ? sBl : sBh) + (((size_t)row) << 13) + kbB
                             + ((size_t)c << 4);
            cp16(st + 16384u + (uint32_t)tile * 8192u + tile_off(row, c), gp);
        }
        asm volatile("cp.async.commit_group;" ::: "memory");
    };

    copy_stage(0, 0);
    copy_stage(1, 1);

    for (int kt = 0; kt < KT; ++kt) {
        if (kt + 1 < KT) asm volatile("cp.async.wait_group 1;" ::: "memory");
        else             asm volatile("cp.async.wait_group 0;" ::: "memory");
        __syncthreads();
        stage_mma(F, sbase + (uint32_t)(kt % 3) * STAGE, wm0, wn0, L);
        if (kt + 2 < KT) copy_stage((kt + 2) % 3, kt + 2);
    }

    float* base = Cp + (size_t)(dom * KSPLIT + z) * NN * DD;
    #pragma unroll
    for (int mi = 0; mi < 2; ++mi) {
        const int r0 = m0 + wm0 + mi * 16 + (L >> 2);
        #pragma unroll
        for (int ni = 0; ni < 8; ++ni) {
            const int col = wn0 + ni * 8 + (L & 3) * 2;
            *(float2*)&base[(size_t)r0 * DD + col] =
                make_float2(F.acc[mi][ni][0], F.acc[mi][ni][1]);
            *(float2*)&base[(size_t)(r0 + 8) * DD + col] =
                make_float2(F.acc[mi][ni][2], F.acc[mi][ni][3]);
        }
    }
}

// ---------------- MLP GEMM: C = act(A[4096,128] @ Wt^T + bias) -----------------
#define KTM 4   // K=128 / BK=32
__global__ void __launch_bounds__(256, 1) tc_mlp(
    const float* __restrict__ A0, const float* __restrict__ A1,
    int wi0, int wi1,
    const float* __restrict__ bias0, const float* __restrict__ bias1,
    float* __restrict__ C0, float* __restrict__ C1, int do_relu)
{
    extern __shared__ char smem[];
    const uint32_t sbase = s2u(smem);
    const int tid = threadIdx.x;
    const int dom = blockIdx.y;
    const int m0 = blockIdx.x * 128;

    const char* sA  = (const char*)(dom ? A1 : A0);
    const char* sBh = (const char*)g_Wth[dom ? wi1 : wi0];
    const char* sBl = (const char*)g_Wtl[dom ? wi1 : wi0];
    const float* __restrict__ bias = dom ? bias1 : bias0;
    float* __restrict__ C = dom ? C1 : C0;

    const int w   = tid >> 5;
    const int L   = tid & 31;
    const int wm0 = (w & 3) * 32;
    const int wn0 = (w >> 2) * 64;

    Frag F;
    #pragma unroll
    for (int i = 0; i < 2; i++)
        #pragma unroll
        for (int j = 0; j < 8; j++)
            #pragma unroll
            for (int q = 0; q < 4; q++) F.acc[i][j][q] = 0.f;

    auto copy_stage = [&](int stage, int kt) {
        const uint32_t st = sbase + (uint32_t)stage * STAGE;
        const size_t kbA = (size_t)kt * 128;
        #pragma unroll
        for (int q = 0; q < 4; ++q) {
            const int idx = q * 256 + tid;
            const int row = idx >> 3;
            const int c   = idx & 7;
            cp16(st + atile_off(row, c),
                 sA + (((size_t)(m0 + row)) << 9) + kbA + ((size_t)c << 4));
        }
        const size_t kbB = (size_t)kt * 64;
        #pragma unroll
        for (int q = 0; q < 4; ++q) {
            const int idx  = q * 256 + tid;
            const int tile = idx >> 9;
            const int rem  = idx & 511;
            const int row  = rem >> 2;
            const int c    = rem & 3;
            const char* gp = (tile ? sBl : sBh) + ((size_t)row << 8) + kbB
                             + ((size_t)c << 4);
            cp16(st + 16384u + (uint32_t)tile * 8192u + tile_off(row, c), gp);
        }
        asm volatile("cp.async.commit_group;" ::: "memory");
    };

    copy_stage(0, 0);
    copy_stage(1, 1);

    for (int kt = 0; kt < KTM; ++kt) {
        if (kt + 1 < KTM) asm volatile("cp.async.wait_group 1;" ::: "memory");
        else              asm volatile("cp.async.wait_group 0;" ::: "memory");
        __syncthreads();
        stage_mma(F, sbase + (uint32_t)(kt % 3) * STAGE, wm0, wn0, L);
        if (kt + 2 < KTM) copy_stage((kt + 2) % 3, kt + 2);
    }

    #pragma unroll
    for (int mi = 0; mi < 2; ++mi) {
        const int r0 = m0 + wm0 + mi * 16 + (L >> 2);
        #pragma unroll
        for (int ni = 0; ni < 8; ++ni) {
            const int col = wn0 + ni * 8 + (L & 3) * 2;
            float b0 = bias[col], b1 = bias[col + 1];
            float v00 = F.acc[mi][ni][0] + b0, v01 = F.acc[mi][ni][1] + b1;
            float v10 = F.acc[mi][ni][2] + b0, v11 = F.acc[mi][ni][3] + b1;
            if (do_relu) {
                v00 = fmaxf(v00, 0.f); v01 = fmaxf(v01, 0.f);
                v10 = fmaxf(v10, 0.f); v11 = fmaxf(v11, 0.f);
            }
            *(float2*)&C[(size_t)r0 * DD + col]       = make_float2(v00, v01);
            *(float2*)&C[(size_t)(r0 + 8) * DD + col] = make_float2(v10, v11);
        }
    }
}

// ---------------- transpose + split: sum of nparts [4096,128] f32 -> [128,4096]
__global__ void __launch_bounds__(256) transpose_split(
    const float* __restrict__ s0, int nparts,
    __nv_bfloat16* __restrict__ hi, __nv_bfloat16* __restrict__ lo)
{
    __shared__ float t[32][33];
    const int tx = threadIdx.x, ty = threadIdx.y;   // block (32, 8)
    #pragma unroll
    for (int j = 0; j < 4; ++j) {
        int r = blockIdx.x * 32 + ty + j * 8;
        int c = blockIdx.y * 32 + tx;
        float v = 0.f;
        for (int p = 0; p < nparts; ++p)
            v += s0[(size_t)p * NN * DD + (size_t)r * DD + c];
        t[ty + j * 8][tx] = v;
    }
    __syncthreads();
    #pragma unroll
    for (int j = 0; j < 4; ++j) {
        int oc = blockIdx.y * 32 + ty + j * 8;
        int orr = blockIdx.x * 32 + tx;
        float v = t[tx][ty + j * 8];
        __nv_bfloat16 h = __float2bfloat16(v);
        hi[(size_t)oc * NN + orr] = h;
        lo[(size_t)oc * NN + orr] = __float2bfloat16(v - __bfloat162float(h));
    }
}

// ---------------- MLP weight transpose+split ------------------------------------
__global__ void __launch_bounds__(256) w_split(
    const float* __restrict__ w0, const float* __restrict__ w1,
    const float* __restrict__ w2, const float* __restrict__ w3)
{
    const float* W = (blockIdx.y == 0) ? w0 : (blockIdx.y == 1) ? w1
                     : (blockIdx.y == 2) ? w2 : w3;
    int idx = blockIdx.x * 256 + threadIdx.x;
    int k = idx >> 7, n = idx & 127;
    float v = W[idx];
    __nv_bfloat16 h = __float2bfloat16(v);
    g_Wth[blockIdx.y][n * DD + k] = h;
    g_Wtl[blockIdx.y][n * DD + k] = __float2bfloat16(v - __bfloat162float(h));
}

// ---------------- review rowsums ------------------------------------------------
__global__ void __launch_bounds__(256) rowsum_kernel(
    const float* __restrict__ revA, const float* __restrict__ revB)
{
    const int dom = blockIdx.y;
    const float* __restrict__ rev = dom ? revB : revA;
    const int row = blockIdx.x * 8 + (threadIdx.x >> 5);
    const int lane = threadIdx.x & 31;
    const float4* p = (const float4*)(rev + (size_t)row * NN);
    float s = 0.f;
    #pragma unroll 4
    for (int j = lane; j < NN / 4; j += 32) {
        float4 v = p[j];
        s += (v.x + v.y) + (v.z + v.w);
    }
    #pragma unroll
    for (int o = 16; o; o >>= 1) s += __shfl_xor_sync(0xffffffffu, s, o);
    if (!lane) g_rowsum[dom][row] = s;
}

// ---------------- Wr colsums ----------------------------------------------------
__global__ void __launch_bounds__(1024) colsum_kernel(
    const float* __restrict__ WrA, const float* __restrict__ WrB)
{
    const int dom = blockIdx.x;
    const float* __restrict__ W = dom ? WrB : WrA;
    __shared__ float sm[8][128];
    const int d = threadIdx.x & 127;
    const int r = threadIdx.x >> 7;
    float s = 0.f;
    for (int k = r; k < NN; k += 8) s += W[k * DD + d];
    sm[r][d] = s;
    __syncthreads();
    if (r == 0) {
        float t = 0.f;
        #pragma unroll
        for (int q = 0; q < 8; q++) t += sm[q][d];
        g_colsum[dom][d] = t;
    }
}

// ---------------- gather + K-split combine + review rank-1 + attention ---------
__global__ void __launch_bounds__(256) gather_combine(
    const int* __restrict__ u, const int* __restrict__ iidx,
    const int* __restrict__ domain_p,
    const float* __restrict__ att_A, const float* __restrict__ att_B)
{
    const int idx = blockIdx.x * 256 + threadIdx.x;
    const int b = idx >> 7, d = idx & 127;
    const int dom = domain_p ? domain_p[0] : 0;
    const int uu = u[b], ii = iidx[b];

    const size_t ud = (size_t)uu * DD + d;
    float sA_ = 0.f, sB_ = 0.f;
    #pragma unroll
    for (int z = 0; z < KSPLIT; ++z) {
        sA_ += g_Cpart[z][ud];
        sB_ += g_Cpart[KSPLIT + z][ud];
    }
    float uA = fmaxf(sA_, 0.f) + fmaxf(g_rowsum[0][uu] * g_colsum[0][d], 0.f);
    float uB = fmaxf(sB_, 0.f) + fmaxf(g_rowsum[1][uu] * g_colsum[1][d], 0.f);

    const size_t id_ = (size_t)ii * DD + d;
    float it = 0.f;
    #pragma unroll
    for (int z = 0; z < KSPLIT; ++z)
        it += g_Cpart[(dom ? KSPLIT : 0) + z][id_];

    float user;
    if (dom == 0) {
        float w = att_A[uu * DD + d];
        user = uA * w + uB * (1.f - w);
    } else {
        float w = att_B[uu * DD + d];
        user = uB * w + uA * (1.f - w);
    }
    g_pre[0][idx] = user;
    g_pre[1][idx] = fmaxf(it, 0.f);
}

// ---------------- launch --------------------------------------------------------
extern "C" void kernel_launch(void* const* d_in, const int* in_sizes, int n_in,
                              void* d_out, int out_size)
{
    const float* rating_A = (const float*)d_in[0];
    const float* rating_B = (const float*)d_in[1];
    const float* review_A = (const float*)d_in[2];
    const float* review_B = (const float*)d_in[3];
    const float* Wg_A = (const float*)d_in[4];
    const float* Wg_B = (const float*)d_in[5];
    const float* Wr_A = (const float*)d_in[6];
    const float* Wr_B = (const float*)d_in[7];
    const float* att_A = (const float*)d_in[8];
    const float* att_B = (const float*)d_in[9];
    const float* uW1 = (const float*)d_in[10];
    const float* ub1 = (const float*)d_in[11];
    const float* uW2 = (const float*)d_in[12];
    const float* ub2 = (const float*)d_in[13];
    const float* iW1 = (const float*)d_in[14];
    const float* ib1 = (const float*)d_in[15];
    const float* iW2 = (const float*)d_in[16];
    const float* ib2 = (const float*)d_in[17];
    const int*   u_idx = (const int*)d_in[18];
    const int*   i_idx = (const int*)d_in[19];
    const int*   domain = (n_in > 20) ? (const int*)d_in[20] : nullptr;

    float* out_user = (float*)d_out;
    float* out_item = (float*)d_out + (size_t)BB * DD;

    __nv_bfloat16 *Bh, *Bl;
    float *Cp, *P0, *Hd0;
    cudaGetSymbolAddress((void**)&Bh, g_Bh);
    cudaGetSymbolAddress((void**)&Bl, g_Bl);
    cudaGetSymbolAddress((void**)&Cp, g_Cpart);
    cudaGetSymbolAddress((void**)&P0, g_pre);
    cudaGetSymbolAddress((void**)&Hd0, g_hid);

    const size_t NBT = (size_t)DD * NN;
    const size_t NCD = (size_t)NN * DD;
    float* P1 = P0 + NCD;
    float* Hd1 = Hd0 + NCD;
    float* CpA = Cp;
    float* CpB = Cp + KSPLIT * NCD;

    // ---- one-time handle creation on the first (uncaptured) call -------------
    static cudaStream_t sB = nullptr, sC = nullptr;
    static cudaEvent_t evFork = nullptr, evB1 = nullptr, evB2 = nullptr,
                       evG1 = nullptr, evC = nullptr;
    if (sB == nullptr) {
        cudaStreamCreateWithFlags(&sB, cudaStreamNonBlocking);
        cudaStreamCreateWithFlags(&sC, cudaStreamNonBlocking);
        cudaEventCreateWithFlags(&evFork, cudaEventDisableTiming);
        cudaEventCreateWithFlags(&evB1,   cudaEventDisableTiming);
        cudaEventCreateWithFlags(&evB2,   cudaEventDisableTiming);
        cudaEventCreateWithFlags(&evG1,   cudaEventDisableTiming);
        cudaEventCreateWithFlags(&evC,    cudaEventDisableTiming);
        cudaFuncSetAttribute(tc_gemm, cudaFuncAttributeMaxDynamicSharedMemorySize, TCG_SMEM);
        cudaFuncSetAttribute(tc_mlp,  cudaFuncAttributeMaxDynamicSharedMemorySize, TCG_SMEM);
        // pre-warm streams/events so lazy driver allocations land pre-baseline
        cudaEventRecord(evFork, MAIN_S);
        cudaStreamWaitEvent(sB, evFork, 0);
        cudaStreamWaitEvent(sC, evFork, 0);
        cudaEventRecord(evB1, sB);
        cudaEventRecord(evB2, sB);
        cudaEventRecord(evC, sC);
        cudaEventRecord(evG1, MAIN_S);
        cudaStreamWaitEvent(MAIN_S, evB1, 0);
        cudaStreamWaitEvent(MAIN_S, evB2, 0);
        cudaStreamWaitEvent(MAIN_S, evC, 0);
        cudaStreamWaitEvent(sB, evG1, 0);
    }

    dim3 blk(256);
    dim3 tsg(NN / 32, DD / 32), tsb(32, 8);
    dim3 gemm_grid(NN / 128, 2, KSPLIT);   // merged: 256 CTAs -> 2 CTAs/SM

    cudaEventRecord(evFork, MAIN_S);
    cudaStreamWaitEvent(sB, evFork, 0);
    cudaStreamWaitEvent(sC, evFork, 0);

    // ---- weight transposes in parallel ----
    transpose_split<<<tsg, tsb, 0, MAIN_S>>>(Wg_A, 1, Bh, Bl);
    transpose_split<<<tsg, tsb, 0, sB>>>(Wg_B, 1, Bh + NBT, Bl + NBT);
    cudaEventRecord(evB1, sB);

    // ---- side work ----
    rowsum_kernel<<<dim3(NN / 8, 2), blk, 0, sC>>>(review_A, review_B);
    colsum_kernel<<<dim3(2), dim3(1024), 0, sC>>>(Wr_A, Wr_B);
    w_split<<<dim3(64, 4), blk, 0, sC>>>(uW1, iW1, uW2, iW2);
    cudaEventRecord(evC, sC);

    // ---- GEMM1 merged (both domains in one grid) ----
    cudaStreamWaitEvent(MAIN_S, evB1, 0);
    tc_gemm<<<gemm_grid, blk, TCG_SMEM, MAIN_S>>>(
        rating_A, rating_B, Bh, Bh + NBT, Bl, Bl + NBT, Cp);
    cudaEventRecord(evG1, MAIN_S);

    // ---- H transposes in parallel ----
    transpose_split<<<tsg, tsb, 0, MAIN_S>>>(CpA, KSPLIT, Bh, Bl);
    cudaStreamWaitEvent(sB, evG1, 0);
    transpose_split<<<tsg, tsb, 0, sB>>>(CpB, KSPLIT, Bh + NBT, Bl + NBT);
    cudaEventRecord(evB2, sB);

    // ---- GEMM2 merged ----
    cudaStreamWaitEvent(MAIN_S, evB2, 0);
    tc_gemm<<<gemm_grid, blk, TCG_SMEM, MAIN_S>>>(
        rating_A, rating_B, Bh, Bh + NBT, Bl, Bl + NBT, Cp);

    // ---- join side work, then gather + MLPs ----
    cudaStreamWaitEvent(MAIN_S, evC, 0);
    gather_combine<<<dim3((BB * DD) / 256), blk, 0, MAIN_S>>>(u_idx, i_idx, domain,
                                                              att_A, att_B);
    tc_mlp<<<dim3(BB / 128, 2), blk, TCG_SMEM, MAIN_S>>>(
        P0, P1, 0, 1, ub1, ib1, Hd0, Hd1, 1);
    tc_mlp<<<dim3(BB / 128, 2), blk, TCG_SMEM, MAIN_S>>>(
        Hd0, Hd1, 2, 3, ub2, ib2, out_user, out_item, 0);
}

// round 11
// speedup vs baseline: 1.2537x; 1.2537x over previous
#include <cuda_runtime.h>
#include <cuda_fp16.h>
#include <cstdint>

#define NN 4096
#define DD 128
#define BB 4096
#define KSPLIT 4
#define KQ (NN / KSPLIT)      // 1024
#define KT (KQ / 32)          // 32 K-iterations of BK=32
#define MAIN_S cudaStreamPerThread

// ---------------- scratch (device globals; no allocation allowed) -------------
__device__ __align__(256) __half g_Bt[2][(size_t)DD * NN];   // B^T fp16 (single)
__device__ __align__(256) __half g_Wth[4][DD * DD];          // W^T hi fp16
__device__ __align__(256) __half g_Wtl[4][DD * DD];          // W^T lo fp16
__device__ __align__(256) float g_Cpart[2 * KSPLIT][(size_t)NN * DD];
__device__ float g_rowsum[2][NN];
__device__ float g_colsum[2][DD];
__device__ float g_pre[2][BB * DD];
__device__ float g_hid[2][BB * DD];

// ---------------- PTX helpers --------------------------------------------------
__device__ __forceinline__ uint32_t s2u(const void* p) {
    return (uint32_t)__cvta_generic_to_shared(p);
}
__device__ __forceinline__ void cp16(uint32_t dst, const void* src) {
    asm volatile("cp.async.cg.shared.global [%0], [%1], 16;" :: "r"(dst), "l"(src));
}
__device__ __forceinline__ void ldsm4(uint32_t& r0, uint32_t& r1, uint32_t& r2,
                                      uint32_t& r3, uint32_t addr) {
    asm volatile("ldmatrix.sync.aligned.m8n8.x4.shared.b16 {%0,%1,%2,%3}, [%4];"
                 : "=r"(r0), "=r"(r1), "=r"(r2), "=r"(r3) : "r"(addr));
}
__device__ __forceinline__ float2 lds64(uint32_t addr) {
    float2 v;
    asm volatile("ld.shared.v2.f32 {%0,%1}, [%2];" : "=f"(v.x), "=f"(v.y) : "r"(addr));
    return v;
}
__device__ __forceinline__ void mma16816(float* c, const uint32_t* a,
                                         uint32_t b0, uint32_t b1) {
    asm volatile(
        "mma.sync.aligned.m16n8k16.row.col.f32.f16.f16.f32 "
        "{%0,%1,%2,%3}, {%4,%5,%6,%7}, {%8,%9}, {%0,%1,%2,%3};"
        : "+f"(c[0]), "+f"(c[1]), "+f"(c[2]), "+f"(c[3])
        : "r"(a[0]), "r"(a[1]), "r"(a[2]), "r"(a[3]), "r"(b0), "r"(b1));
}
// fp16 exact-A split: v -> packed f16x2 hi + lo (A = hi + lo to ~2^-23)
__device__ __forceinline__ void cvt_split(float2 v, uint32_t& h, uint32_t& l) {
    __half2 hh = __floats2half2_rn(v.x, v.y);
    float2 f = __half22float2(hh);
    __half2 ll = __floats2half2_rn(v.x - f.x, v.y - f.y);
    h = *(uint32_t*)&hh;
    l = *(uint32_t*)&ll;
}

// fp16 B tile: 128 rows x 32 f16 (64B rows), 16B chunk c (0..3), swizzled
__device__ __forceinline__ uint32_t tile_off(int row, int c) {
    return (uint32_t)(row * 64 + ((c ^ ((row >> 1) & 3)) << 4));
}
// fp32 A tile: 128 rows x 32 f32 (128B rows), 16B chunk c (0..7), swizzled
__device__ __forceinline__ uint32_t atile_off(int row, int c) {
    return (uint32_t)(row * 128 + ((c ^ ((row & 3) << 1)) << 4));
}
__device__ __forceinline__ uint32_t atile_addr(int row, int c2) {
    int b = c2 * 4;
    return (uint32_t)(row * 128 + (((b >> 4) ^ ((row & 3) << 1)) << 4) + (b & 15));
}

#define STAGE_G 24576u          // big GEMM: A f32 16KB | B f16 8KB
#define TCG_SMEM_G (3 * STAGE_G)   // 73728 (2 CTAs/SM fits)
#define STAGE_M 32768u          // MLP: A f32 16KB | Bh 8KB | Bl 8KB
#define TCG_SMEM_M (3 * STAGE_M)   // 98304

struct Frag { float acc[2][8][4]; };

// ---------------- big-GEMM stage: A(fp32->Ah+Al fp16, exact) x B(fp16) ---------
__device__ __forceinline__ void stage_mma2(Frag& F, uint32_t st, int wm0, int wn0, int L) {
    const uint32_t stB = st + 16384u;
    #pragma unroll
    for (int ks = 0; ks < 2; ++ks) {
        uint32_t ah[2][4], al[2][4];
        {
            const int r  = wm0 + (L >> 2);
            const int c2 = (L & 3) * 2 + ks * 16;
            #pragma unroll
            for (int mi = 0; mi < 2; ++mi) {
                const int rr = r + mi * 16;
                float2 v00 = lds64(st + atile_addr(rr,     c2));
                float2 v10 = lds64(st + atile_addr(rr + 8, c2));
                float2 v01 = lds64(st + atile_addr(rr,     c2 + 8));
                float2 v11 = lds64(st + atile_addr(rr + 8, c2 + 8));
                cvt_split(v00, ah[mi][0], al[mi][0]);
                cvt_split(v10, ah[mi][1], al[mi][1]);
                cvt_split(v01, ah[mi][2], al[mi][2]);
                cvt_split(v11, ah[mi][3], al[mi][3]);
            }
        }
        const int rb = wn0 + (L & 7) + ((L & 16) >> 1);
        const int hc = (L >> 3) & 1;
        #pragma unroll
        for (int pi = 0; pi < 4; ++pi) {
            uint32_t bb[4];
            const uint32_t off = tile_off(rb + pi * 16, ks * 2 + hc);
            ldsm4(bb[0], bb[1], bb[2], bb[3], stB + off);
            #pragma unroll
            for (int mi = 0; mi < 2; ++mi) {
                #pragma unroll
                for (int half = 0; half < 2; ++half) {
                    float* c = F.acc[mi][pi * 2 + half];
                    mma16816(c, ah[mi], bb[half * 2], bb[half * 2 + 1]);
                    mma16816(c, al[mi], bb[half * 2], bb[half * 2 + 1]);
                }
            }
        }
    }
}

// ---------------- MLP stage: 3-term fp16 (negligible error) --------------------
__device__ __forceinline__ void stage_mma3(Frag& F, uint32_t st, int wm0, int wn0, int L) {
    const uint32_t stBh = st + 16384u;
    const uint32_t stBl = st + 24576u;
    #pragma unroll
    for (int ks = 0; ks < 2; ++ks) {
        uint32_t ah[2][4], al[2][4];
        {
            const int r  = wm0 + (L >> 2);
            const int c2 = (L & 3) * 2 + ks * 16;
            #pragma unroll
            for (int mi = 0; mi < 2; ++mi) {
                const int rr = r + mi * 16;
                float2 v00 = lds64(st + atile_addr(rr,     c2));
                float2 v10 = lds64(st + atile_addr(rr + 8, c2));
                float2 v01 = lds64(st + atile_addr(rr,     c2 + 8));
                float2 v11 = lds64(st + atile_addr(rr + 8, c2 + 8));
                cvt_split(v00, ah[mi][0], al[mi][0]);
                cvt_split(v10, ah[mi][1], al[mi][1]);
                cvt_split(v01, ah[mi][2], al[mi][2]);
                cvt_split(v11, ah[mi][3], al[mi][3]);
            }
        }
        const int rb = wn0 + (L & 7) + ((L & 16) >> 1);
        const int hc = (L >> 3) & 1;
        #pragma unroll
        for (int pi = 0; pi < 4; ++pi) {
            uint32_t bh[4], bl[4];
            const uint32_t off = tile_off(rb + pi * 16, ks * 2 + hc);
            ldsm4(bh[0], bh[1], bh[2], bh[3], stBh + off);
            ldsm4(bl[0], bl[1], bl[2], bl[3], stBl + off);
            #pragma unroll
            for (int mi = 0; mi < 2; ++mi) {
                #pragma unroll
                for (int half = 0; half < 2; ++half) {
                    float* c = F.acc[mi][pi * 2 + half];
                    mma16816(c, ah[mi], bh[half * 2], bh[half * 2 + 1]);
                    mma16816(c, ah[mi], bl[half * 2], bl[half * 2 + 1]);
                    mma16816(c, al[mi], bh[half * 2], bh[half * 2 + 1]);
                }
            }
        }
    }
}

// ---------------- single-domain fp16 2-term GEMM (K-split 4) -------------------
__global__ void __launch_bounds__(256, 2) tc_gemm(
    const float* __restrict__ A,
    const __half* __restrict__ Bt,
    float* __restrict__ Cp)   // Cp: KSPLIT partials of [NN, DD]
{
    extern __shared__ char smem[];
    const uint32_t sbase = s2u(smem);
    const int tid = threadIdx.x;
    const int z = blockIdx.z;
    const int m0 = blockIdx.x * 128;

    const char* sA = (const char*)A;
    const char* sB = (const char*)Bt;

    const int w   = tid >> 5;
    const int L   = tid & 31;
    const int wm0 = (w & 3) * 32;
    const int wn0 = (w >> 2) * 64;

    Frag F;
    #pragma unroll
    for (int i = 0; i < 2; i++)
        #pragma unroll
        for (int j = 0; j < 8; j++)
            #pragma unroll
            for (int q = 0; q < 4; q++) F.acc[i][j][q] = 0.f;

    auto copy_stage = [&](int stage, int kt) {
        const uint32_t st = sbase + (uint32_t)stage * STAGE_G;
        const size_t kbA = ((size_t)(z * KQ + kt * 32)) * 4;
        #pragma unroll
        for (int q = 0; q < 4; ++q) {
            const int idx = q * 256 + tid;      // 0..1023 A chunks
            const int row = idx >> 3;
            const int c   = idx & 7;
            cp16(st + atile_off(row, c),
                 sA + (((size_t)(m0 + row)) << 14) + kbA + ((size_t)c << 4));
        }
        const size_t kbB = ((size_t)(z * KQ + kt * 32)) * 2;
        #pragma unroll
        for (int q = 0; q < 2; ++q) {
            const int idx = q * 256 + tid;      // 0..511 B chunks
            const int row = idx >> 2;
            const int c   = idx & 3;
            cp16(st + 16384u + tile_off(row, c),
                 sB + (((size_t)row) << 13) + kbB + ((size_t)c << 4));
        }
        asm volatile("cp.async.commit_group;" ::: "memory");
    };

    copy_stage(0, 0);
    copy_stage(1, 1);

    for (int kt = 0; kt < KT; ++kt) {
        if (kt + 1 < KT) asm volatile("cp.async.wait_group 1;" ::: "memory");
        else             asm volatile("cp.async.wait_group 0;" ::: "memory");
        __syncthreads();
        stage_mma2(F, sbase + (uint32_t)(kt % 3) * STAGE_G, wm0, wn0, L);
        if (kt + 2 < KT) copy_stage((kt + 2) % 3, kt + 2);
    }

    float* base = Cp + (size_t)z * NN * DD;
    #pragma unroll
    for (int mi = 0; mi < 2; ++mi) {
        const int r0 = m0 + wm0 + mi * 16 + (L >> 2);
        #pragma unroll
        for (int ni = 0; ni < 8; ++ni) {
            const int col = wn0 + ni * 8 + (L & 3) * 2;
            *(float2*)&base[(size_t)r0 * DD + col] =
                make_float2(F.acc[mi][ni][0], F.acc[mi][ni][1]);
            *(float2*)&base[(size_t)(r0 + 8) * DD + col] =
                make_float2(F.acc[mi][ni][2], F.acc[mi][ni][3]);
        }
    }
}

// ---------------- MLP GEMM: C = act(A[4096,128] @ Wt^T + bias), 3-term fp16 ----
#define KTM 4   // K=128 / BK=32
__global__ void __launch_bounds__(256, 1) tc_mlp(
    const float* __restrict__ A0, const float* __restrict__ A1,
    int wi0, int wi1,
    const float* __restrict__ bias0, const float* __restrict__ bias1,
    float* __restrict__ C0, float* __restrict__ C1, int do_relu)
{
    extern __shared__ char smem[];
    const uint32_t sbase = s2u(smem);
    const int tid = threadIdx.x;
    const int dom = blockIdx.y;
    const int m0 = blockIdx.x * 128;

    const char* sA  = (const char*)(dom ? A1 : A0);
    const char* sBh = (const char*)g_Wth[dom ? wi1 : wi0];
    const char* sBl = (const char*)g_Wtl[dom ? wi1 : wi0];
    const float* __restrict__ bias = dom ? bias1 : bias0;
    float* __restrict__ C = dom ? C1 : C0;

    const int w   = tid >> 5;
    const int L   = tid & 31;
    const int wm0 = (w & 3) * 32;
    const int wn0 = (w >> 2) * 64;

    Frag F;
    #pragma unroll
    for (int i = 0; i < 2; i++)
        #pragma unroll
        for (int j = 0; j < 8; j++)
            #pragma unroll
            for (int q = 0; q < 4; q++) F.acc[i][j][q] = 0.f;

    auto copy_stage = [&](int stage, int kt) {
        const uint32_t st = sbase + (uint32_t)stage * STAGE_M;
        const size_t kbA = (size_t)kt * 128;
        #pragma unroll
        for (int q = 0; q < 4; ++q) {
            const int idx = q * 256 + tid;
            const int row = idx >> 3;
            const int c   = idx & 7;
            cp16(st + atile_off(row, c),
                 sA + (((size_t)(m0 + row)) << 9) + kbA + ((size_t)c << 4));
        }
        const size_t kbB = (size_t)kt * 64;
        #pragma unroll
        for (int q = 0; q < 4; ++q) {
            const int idx  = q * 256 + tid;
            const int tile = idx >> 9;
            const int rem  = idx & 511;
            const int row  = rem >> 2;
            const int c    = rem & 3;
            const char* gp = (tile ? sBl : sBh) + ((size_t)row << 8) + kbB
                             + ((size_t)c << 4);
            cp16(st + 16384u + (uint32_t)tile * 8192u + tile_off(row, c), gp);
        }
        asm volatile("cp.async.commit_group;" ::: "memory");
    };

    copy_stage(0, 0);
    copy_stage(1, 1);

    for (int kt = 0; kt < KTM; ++kt) {
        if (kt + 1 < KTM) asm volatile("cp.async.wait_group 1;" ::: "memory");
        else              asm volatile("cp.async.wait_group 0;" ::: "memory");
        __syncthreads();
        stage_mma3(F, sbase + (uint32_t)(kt % 3) * STAGE_M, wm0, wn0, L);
        if (kt + 2 < KTM) copy_stage((kt + 2) % 3, kt + 2);
    }

    #pragma unroll
    for (int mi = 0; mi < 2; ++mi) {
        const int r0 = m0 + wm0 + mi * 16 + (L >> 2);
        #pragma unroll
        for (int ni = 0; ni < 8; ++ni) {
            const int col = wn0 + ni * 8 + (L & 3) * 2;
            float b0 = bias[col], b1 = bias[col + 1];
            float v00 = F.acc[mi][ni][0] + b0, v01 = F.acc[mi][ni][1] + b1;
            float v10 = F.acc[mi][ni][2] + b0, v11 = F.acc[mi][ni][3] + b1;
            if (do_relu) {
                v00 = fmaxf(v00, 0.f); v01 = fmaxf(v01, 0.f);
                v10 = fmaxf(v10, 0.f); v11 = fmaxf(v11, 0.f);
            }
            *(float2*)&C[(size_t)r0 * DD + col]       = make_float2(v00, v01);
            *(float2*)&C[(size_t)(r0 + 8) * DD + col] = make_float2(v10, v11);
        }
    }
}

// ---------------- transpose: sum of nparts [4096,128] f32 -> [128,4096] fp16 ---
__global__ void __launch_bounds__(256) transpose_half(
    const float* __restrict__ s0, int nparts, __half* __restrict__ out)
{
    __shared__ float t[32][33];
    const int tx = threadIdx.x, ty = threadIdx.y;   // block (32, 8)
    #pragma unroll
    for (int j = 0; j < 4; ++j) {
        int r = blockIdx.x * 32 + ty + j * 8;
        int c = blockIdx.y * 32 + tx;
        float v = 0.f;
        for (int p = 0; p < nparts; ++p)
            v += s0[(size_t)p * NN * DD + (size_t)r * DD + c];
        t[ty + j * 8][tx] = v;
    }
    __syncthreads();
    #pragma unroll
    for (int j = 0; j < 4; ++j) {
        int oc = blockIdx.y * 32 + ty + j * 8;
        int orr = blockIdx.x * 32 + tx;
        out[(size_t)oc * NN + orr] = __float2half(t[tx][ty + j * 8]);
    }
}

// ---------------- MLP weight transpose+split (fp16 hi/lo) ----------------------
__global__ void __launch_bounds__(256) w_split(
    const float* __restrict__ w0, const float* __restrict__ w1,
    const float* __restrict__ w2, const float* __restrict__ w3)
{
    const float* W = (blockIdx.y == 0) ? w0 : (blockIdx.y == 1) ? w1
                     : (blockIdx.y == 2) ? w2 : w3;
    int idx = blockIdx.x * 256 + threadIdx.x;
    int k = idx >> 7, n = idx & 127;
    float v = W[idx];
    __half h = __float2half(v);
    g_Wth[blockIdx.y][n * DD + k] = h;
    g_Wtl[blockIdx.y][n * DD + k] = __float2half(v - __half2float(h));
}

// ---------------- review rowsums ------------------------------------------------
__global__ void __launch_bounds__(256) rowsum_kernel(
    const float* __restrict__ revA, const float* __restrict__ revB)
{
    const int dom = blockIdx.y;
    const float* __restrict__ rev = dom ? revB : revA;
    const int row = blockIdx.x * 8 + (threadIdx.x >> 5);
    const int lane = threadIdx.x & 31;
    const float4* p = (const float4*)(rev + (size_t)row * NN);
    float s = 0.f;
    #pragma unroll 4
    for (int j = lane; j < NN / 4; j += 32) {
        float4 v = p[j];
        s += (v.x + v.y) + (v.z + v.w);
    }
    #pragma unroll
    for (int o = 16; o; o >>= 1) s += __shfl_xor_sync(0xffffffffu, s, o);
    if (!lane) g_rowsum[dom][row] = s;
}

// ---------------- Wr colsums ----------------------------------------------------
__global__ void __launch_bounds__(1024) colsum_kernel(
    const float* __restrict__ WrA, const float* __restrict__ WrB)
{
    const int dom = blockIdx.x;
    const float* __restrict__ W = dom ? WrB : WrA;
    __shared__ float sm[8][128];
    const int d = threadIdx.x & 127;
    const int r = threadIdx.x >> 7;
    float s = 0.f;
    for (int k = r; k < NN; k += 8) s += W[k * DD + d];
    sm[r][d] = s;
    __syncthreads();
    if (r == 0) {
        float t = 0.f;
        #pragma unroll
        for (int q = 0; q < 8; q++) t += sm[q][d];
        g_colsum[dom][d] = t;
    }
}

// ---------------- gather + K-split combine + review rank-1 + attention ---------
__global__ void __launch_bounds__(256) gather_combine(
    const int* __restrict__ u, const int* __restrict__ iidx,
    const int* __restrict__ domain_p,
    const float* __restrict__ att_A, const float* __restrict__ att_B)
{
    const int idx = blockIdx.x * 256 + threadIdx.x;
    const int b = idx >> 7, d = idx & 127;
    const int dom = domain_p ? domain_p[0] : 0;
    const int uu = u[b], ii = iidx[b];

    const size_t ud = (size_t)uu * DD + d;
    float sA_ = 0.f, sB_ = 0.f;
    #pragma unroll
    for (int z = 0; z < KSPLIT; ++z) {
        sA_ += g_Cpart[z][ud];
        sB_ += g_Cpart[KSPLIT + z][ud];
    }
    float uA = fmaxf(sA_, 0.f) + fmaxf(g_rowsum[0][uu] * g_colsum[0][d], 0.f);
    float uB = fmaxf(sB_, 0.f) + fmaxf(g_rowsum[1][uu] * g_colsum[1][d], 0.f);

    const size_t id_ = (size_t)ii * DD + d;
    float it = 0.f;
    #pragma unroll
    for (int z = 0; z < KSPLIT; ++z)
        it += g_Cpart[(dom ? KSPLIT : 0) + z][id_];

    float user;
    if (dom == 0) {
        float w = att_A[uu * DD + d];
        user = uA * w + uB * (1.f - w);
    } else {
        float w = att_B[uu * DD + d];
        user = uB * w + uA * (1.f - w);
    }
    g_pre[0][idx] = user;
    g_pre[1][idx] = fmaxf(it, 0.f);
}

// ---------------- launch --------------------------------------------------------
extern "C" void kernel_launch(void* const* d_in, const int* in_sizes, int n_in,
                              void* d_out, int out_size)
{
    const float* rating_A = (const float*)d_in[0];
    const float* rating_B = (const float*)d_in[1];
    const float* review_A = (const float*)d_in[2];
    const float* review_B = (const float*)d_in[3];
    const float* Wg_A = (const float*)d_in[4];
    const float* Wg_B = (const float*)d_in[5];
    const float* Wr_A = (const float*)d_in[6];
    const float* Wr_B = (const float*)d_in[7];
    const float* att_A = (const float*)d_in[8];
    const float* att_B = (const float*)d_in[9];
    const float* uW1 = (const float*)d_in[10];
    const float* ub1 = (const float*)d_in[11];
    const float* uW2 = (const float*)d_in[12];
    const float* ub2 = (const float*)d_in[13];
    const float* iW1 = (const float*)d_in[14];
    const float* ib1 = (const float*)d_in[15];
    const float* iW2 = (const float*)d_in[16];
    const float* ib2 = (const float*)d_in[17];
    const int*   u_idx = (const int*)d_in[18];
    const int*   i_idx = (const int*)d_in[19];
    const int*   domain = (n_in > 20) ? (const int*)d_in[20] : nullptr;

    float* out_user = (float*)d_out;
    float* out_item = (float*)d_out + (size_t)BB * DD;

    __half* Bt;
    float *Cp, *P0, *Hd0;
    cudaGetSymbolAddress((void**)&Bt, g_Bt);
    cudaGetSymbolAddress((void**)&Cp, g_Cpart);
    cudaGetSymbolAddress((void**)&P0, g_pre);
    cudaGetSymbolAddress((void**)&Hd0, g_hid);

    const size_t NBT = (size_t)DD * NN;
    const size_t NCD = (size_t)NN * DD;
    float* P1 = P0 + NCD;
    float* Hd1 = Hd0 + NCD;
    float* CpA = Cp;
    float* CpB = Cp + KSPLIT * NCD;

    // ---- one-time handle creation on the first (uncaptured) call -------------
    static cudaStream_t sB = nullptr, sC = nullptr;
    static cudaEvent_t evFork = nullptr, evB = nullptr, evC = nullptr;
    if (sB == nullptr) {
        cudaStreamCreateWithFlags(&sB, cudaStreamNonBlocking);
        cudaStreamCreateWithFlags(&sC, cudaStreamNonBlocking);
        cudaEventCreateWithFlags(&evFork, cudaEventDisableTiming);
        cudaEventCreateWithFlags(&evB,    cudaEventDisableTiming);
        cudaEventCreateWithFlags(&evC,    cudaEventDisableTiming);
        cudaFuncSetAttribute(tc_gemm, cudaFuncAttributeMaxDynamicSharedMemorySize, TCG_SMEM_G);
        cudaFuncSetAttribute(tc_mlp,  cudaFuncAttributeMaxDynamicSharedMemorySize, TCG_SMEM_M);
        // pre-warm streams/events so lazy driver allocations land pre-baseline
        cudaEventRecord(evFork, MAIN_S);
        cudaStreamWaitEvent(sB, evFork, 0);
        cudaStreamWaitEvent(sC, evFork, 0);
        cudaEventRecord(evB, sB);
        cudaEventRecord(evC, sC);
        cudaStreamWaitEvent(MAIN_S, evB, 0);
        cudaStreamWaitEvent(MAIN_S, evC, 0);
    }

    dim3 blk(256);
    dim3 tsg(NN / 32, DD / 32), tsb(32, 8);
    dim3 gemm_grid(NN / 128, 1, KSPLIT);

    cudaEventRecord(evFork, MAIN_S);
    cudaStreamWaitEvent(sB, evFork, 0);
    cudaStreamWaitEvent(sC, evFork, 0);

    // ---- domain A chain (MAIN_S) ----
    transpose_half<<<tsg, tsb, 0, MAIN_S>>>(Wg_A, 1, Bt);
    tc_gemm<<<gemm_grid, blk, TCG_SMEM_G, MAIN_S>>>(rating_A, Bt, CpA);
    transpose_half<<<tsg, tsb, 0, MAIN_S>>>(CpA, KSPLIT, Bt);
    tc_gemm<<<gemm_grid, blk, TCG_SMEM_G, MAIN_S>>>(rating_A, Bt, CpA);

    // ---- domain B chain (sB) ----
    transpose_half<<<tsg, tsb, 0, sB>>>(Wg_B, 1, Bt + NBT);
    tc_gemm<<<gemm_grid, blk, TCG_SMEM_G, sB>>>(rating_B, Bt + NBT, CpB);
    transpose_half<<<tsg, tsb, 0, sB>>>(CpB, KSPLIT, Bt + NBT);
    tc_gemm<<<gemm_grid, blk, TCG_SMEM_G, sB>>>(rating_B, Bt + NBT, CpB);
    cudaEventRecord(evB, sB);

    // ---- side work (sC) ----
    rowsum_kernel<<<dim3(NN / 8, 2), blk, 0, sC>>>(review_A, review_B);
    colsum_kernel<<<dim3(2), dim3(1024), 0, sC>>>(Wr_A, Wr_B);
    w_split<<<dim3(64, 4), blk, 0, sC>>>(uW1, iW1, uW2, iW2);
    cudaEventRecord(evC, sC);

    // ---- join, then gather + MLPs on MAIN_S ----
    cudaStreamWaitEvent(MAIN_S, evB, 0);
    cudaStreamWaitEvent(MAIN_S, evC, 0);

    gather_combine<<<dim3((BB * DD) / 256), blk, 0, MAIN_S>>>(u_idx, i_idx, domain,
                                                              att_A, att_B);
    tc_mlp<<<dim3(BB / 128, 2), blk, TCG_SMEM_M, MAIN_S>>>(
        P0, P1, 0, 1, ub1, ib1, Hd0, Hd1, 1);
    tc_mlp<<<dim3(BB / 128, 2), blk, TCG_SMEM_M, MAIN_S>>>(
        Hd0, Hd1, 2, 3, ub2, ib2, out_user, out_item, 0);
}

// round 12
// speedup vs baseline: 1.5906x; 1.2688x over previous
#include <cuda_runtime.h>
#include <cuda_fp16.h>
#include <cstdint>

#define NN 4096
#define DD 128
#define BB 4096
#define KSPLIT 4
#define KQ (NN / KSPLIT)      // 1024
#define KT (KQ / 32)          // 32 K-iterations of BK=32
#define MAIN_S cudaStreamPerThread

// ---------------- scratch (device globals; no allocation allowed) -------------
__device__ __align__(256) __half g_Bt[2][(size_t)DD * NN];   // B^T fp16 (single)
__device__ __align__(256) __half g_Wth[4][DD * DD];          // W^T hi fp16
__device__ __align__(256) __half g_Wtl[4][DD * DD];          // W^T lo fp16
__device__ __align__(256) float g_Cpart[2 * KSPLIT][(size_t)NN * DD];
__device__ float g_rowsum[2][NN];
__device__ float g_colsum[2][DD];
__device__ float g_pre[2][BB * DD];
__device__ float g_hid[2][BB * DD];

// ---------------- PTX helpers --------------------------------------------------
__device__ __forceinline__ uint32_t s2u(const void* p) {
    return (uint32_t)__cvta_generic_to_shared(p);
}
__device__ __forceinline__ void cp16(uint32_t dst, const void* src) {
    asm volatile("cp.async.cg.shared.global [%0], [%1], 16;" :: "r"(dst), "l"(src));
}
__device__ __forceinline__ void ldsm4(uint32_t& r0, uint32_t& r1, uint32_t& r2,
                                      uint32_t& r3, uint32_t addr) {
    asm volatile("ldmatrix.sync.aligned.m8n8.x4.shared.b16 {%0,%1,%2,%3}, [%4];"
                 : "=r"(r0), "=r"(r1), "=r"(r2), "=r"(r3) : "r"(addr));
}
__device__ __forceinline__ float2 lds64(uint32_t addr) {
    float2 v;
    asm volatile("ld.shared.v2.f32 {%0,%1}, [%2];" : "=f"(v.x), "=f"(v.y) : "r"(addr));
    return v;
}
__device__ __forceinline__ void mma16816(float* c, const uint32_t* a,
                                         uint32_t b0, uint32_t b1) {
    asm volatile(
        "mma.sync.aligned.m16n8k16.row.col.f32.f16.f16.f32 "
        "{%0,%1,%2,%3}, {%4,%5,%6,%7}, {%8,%9}, {%0,%1,%2,%3};"
        : "+f"(c[0]), "+f"(c[1]), "+f"(c[2]), "+f"(c[3])
        : "r"(a[0]), "r"(a[1]), "r"(a[2]), "r"(a[3]), "r"(b0), "r"(b1));
}
// single fp16 round of a float2 (1 instruction)
__device__ __forceinline__ void cvt_hi(float2 v, uint32_t& h) {
    __half2 hh = __floats2half2_rn(v.x, v.y);
    h = *(uint32_t*)&hh;
}
// fp16 exact split (MLP path only)
__device__ __forceinline__ void cvt_split(float2 v, uint32_t& h, uint32_t& l) {
    __half2 hh = __floats2half2_rn(v.x, v.y);
    float2 f = __half22float2(hh);
    __half2 ll = __floats2half2_rn(v.x - f.x, v.y - f.y);
    h = *(uint32_t*)&hh;
    l = *(uint32_t*)&ll;
}

// fp16 B tile: 128 rows x 32 f16 (64B rows), 16B chunk c (0..3), swizzled
__device__ __forceinline__ uint32_t tile_off(int row, int c) {
    return (uint32_t)(row * 64 + ((c ^ ((row >> 1) & 3)) << 4));
}
// fp32 A tile: 128 rows x 32 f32 (128B rows), 16B chunk c (0..7), swizzled
__device__ __forceinline__ uint32_t atile_off(int row, int c) {
    return (uint32_t)(row * 128 + ((c ^ ((row & 3) << 1)) << 4));
}
__device__ __forceinline__ uint32_t atile_addr(int row, int c2) {
    int b = c2 * 4;
    return (uint32_t)(row * 128 + (((b >> 4) ^ ((row & 3) << 1)) << 4) + (b & 15));
}

#define STAGE_G 24576u             // big GEMM: A f32 16KB | B f16 8KB
#define TCG_SMEM_G (3 * STAGE_G)   // 73728 (2 CTAs/SM fits)
#define STAGE_M 32768u             // MLP: A f32 16KB | Bh 8KB | Bl 8KB
#define TCG_SMEM_M (3 * STAGE_M)   // 98304

struct Frag { float acc[2][8][4]; };

// ---------------- big-GEMM stage: 1-term fp16 (A rounded, B fp16) --------------
__device__ __forceinline__ void stage_mma1(Frag& F, uint32_t st, int wm0, int wn0, int L) {
    const uint32_t stB = st + 16384u;
    #pragma unroll
    for (int ks = 0; ks < 2; ++ks) {
        uint32_t ah[2][4];
        {
            const int r  = wm0 + (L >> 2);
            const int c2 = (L & 3) * 2 + ks * 16;
            #pragma unroll
            for (int mi = 0; mi < 2; ++mi) {
                const int rr = r + mi * 16;
                cvt_hi(lds64(st + atile_addr(rr,     c2)),     ah[mi][0]);
                cvt_hi(lds64(st + atile_addr(rr + 8, c2)),     ah[mi][1]);
                cvt_hi(lds64(st + atile_addr(rr,     c2 + 8)), ah[mi][2]);
                cvt_hi(lds64(st + atile_addr(rr + 8, c2 + 8)), ah[mi][3]);
            }
        }
        const int rb = wn0 + (L & 7) + ((L & 16) >> 1);
        const int hc = (L >> 3) & 1;
        #pragma unroll
        for (int pi = 0; pi < 4; ++pi) {
            uint32_t bb[4];
            const uint32_t off = tile_off(rb + pi * 16, ks * 2 + hc);
            ldsm4(bb[0], bb[1], bb[2], bb[3], stB + off);
            #pragma unroll
            for (int mi = 0; mi < 2; ++mi) {
                #pragma unroll
                for (int half = 0; half < 2; ++half) {
                    mma16816(F.acc[mi][pi * 2 + half], ah[mi],
                             bb[half * 2], bb[half * 2 + 1]);
                }
            }
        }
    }
}

// ---------------- MLP stage: 3-term fp16 (negligible error) --------------------
__device__ __forceinline__ void stage_mma3(Frag& F, uint32_t st, int wm0, int wn0, int L) {
    const uint32_t stBh = st + 16384u;
    const uint32_t stBl = st + 24576u;
    #pragma unroll
    for (int ks = 0; ks < 2; ++ks) {
        uint32_t ah[2][4], al[2][4];
        {
            const int r  = wm0 + (L >> 2);
            const int c2 = (L & 3) * 2 + ks * 16;
            #pragma unroll
            for (int mi = 0; mi < 2; ++mi) {
                const int rr = r + mi * 16;
                float2 v00 = lds64(st + atile_addr(rr,     c2));
                float2 v10 = lds64(st + atile_addr(rr + 8, c2));
                float2 v01 = lds64(st + atile_addr(rr,     c2 + 8));
                float2 v11 = lds64(st + atile_addr(rr + 8, c2 + 8));
                cvt_split(v00, ah[mi][0], al[mi][0]);
                cvt_split(v10, ah[mi][1], al[mi][1]);
                cvt_split(v01, ah[mi][2], al[mi][2]);
                cvt_split(v11, ah[mi][3], al[mi][3]);
            }
        }
        const int rb = wn0 + (L & 7) + ((L & 16) >> 1);
        const int hc = (L >> 3) & 1;
        #pragma unroll
        for (int pi = 0; pi < 4; ++pi) {
            uint32_t bh[4], bl[4];
            const uint32_t off = tile_off(rb + pi * 16, ks * 2 + hc);
            ldsm4(bh[0], bh[1], bh[2], bh[3], stBh + off);
            ldsm4(bl[0], bl[1], bl[2], bl[3], stBl + off);
            #pragma unroll
            for (int mi = 0; mi < 2; ++mi) {
                #pragma unroll
                for (int half = 0; half < 2; ++half) {
                    float* c = F.acc[mi][pi * 2 + half];
                    mma16816(c, ah[mi], bh[half * 2], bh[half * 2 + 1]);
                    mma16816(c, ah[mi], bl[half * 2], bl[half * 2 + 1]);
                    mma16816(c, al[mi], bh[half * 2], bh[half * 2 + 1]);
                }
            }
        }
    }
}

// ---------------- single-domain fp16 1-term GEMM (K-split 4) -------------------
__global__ void __launch_bounds__(256, 2) tc_gemm(
    const float* __restrict__ A,
    const __half* __restrict__ Bt,
    float* __restrict__ Cp)   // Cp: KSPLIT partials of [NN, DD]
{
    extern __shared__ char smem[];
    const uint32_t sbase = s2u(smem);
    const int tid = threadIdx.x;
    const int z = blockIdx.z;
    const int m0 = blockIdx.x * 128;

    const char* sA = (const char*)A;
    const char* sB = (const char*)Bt;

    const int w   = tid >> 5;
    const int L   = tid & 31;
    const int wm0 = (w & 3) * 32;
    const int wn0 = (w >> 2) * 64;

    Frag F;
    #pragma unroll
    for (int i = 0; i < 2; i++)
        #pragma unroll
        for (int j = 0; j < 8; j++)
            #pragma unroll
            for (int q = 0; q < 4; q++) F.acc[i][j][q] = 0.f;

    auto copy_stage = [&](int stage, int kt) {
        const uint32_t st = sbase + (uint32_t)stage * STAGE_G;
        const size_t kbA = ((size_t)(z * KQ + kt * 32)) * 4;
        #pragma unroll
        for (int q = 0; q < 4; ++q) {
            const int idx = q * 256 + tid;      // 0..1023 A chunks
            const int row = idx >> 3;
            const int c   = idx & 7;
            cp16(st + atile_off(row, c),
                 sA + (((size_t)(m0 + row)) << 14) + kbA + ((size_t)c << 4));
        }
        const size_t kbB = ((size_t)(z * KQ + kt * 32)) * 2;
        #pragma unroll
        for (int q = 0; q < 2; ++q) {
            const int idx = q * 256 + tid;      // 0..511 B chunks
            const int row = idx >> 2;
            const int c   = idx & 3;
            cp16(st + 16384u + tile_off(row, c),
                 sB + (((size_t)row) << 13) + kbB + ((size_t)c << 4));
        }
        asm volatile("cp.async.commit_group;" ::: "memory");
    };

    copy_stage(0, 0);
    copy_stage(1, 1);

    for (int kt = 0; kt < KT; ++kt) {
        if (kt + 1 < KT) asm volatile("cp.async.wait_group 1;" ::: "memory");
        else             asm volatile("cp.async.wait_group 0;" ::: "memory");
        __syncthreads();
        stage_mma1(F, sbase + (uint32_t)(kt % 3) * STAGE_G, wm0, wn0, L);
        if (kt + 2 < KT) copy_stage((kt + 2) % 3, kt + 2);
    }

    float* base = Cp + (size_t)z * NN * DD;
    #pragma unroll
    for (int mi = 0; mi < 2; ++mi) {
        const int r0 = m0 + wm0 + mi * 16 + (L >> 2);
        #pragma unroll
        for (int ni = 0; ni < 8; ++ni) {
            const int col = wn0 + ni * 8 + (L & 3) * 2;
            *(float2*)&base[(size_t)r0 * DD + col] =
                make_float2(F.acc[mi][ni][0], F.acc[mi][ni][1]);
            *(float2*)&base[(size_t)(r0 + 8) * DD + col] =
                make_float2(F.acc[mi][ni][2], F.acc[mi][ni][3]);
        }
    }
}

// ---------------- MLP GEMM: C = act(A[4096,128] @ Wt^T + bias), 3-term fp16 ----
#define KTM 4   // K=128 / BK=32
__global__ void __launch_bounds__(256, 1) tc_mlp(
    const float* __restrict__ A0, const float* __restrict__ A1,
    int wi0, int wi1,
    const float* __restrict__ bias0, const float* __restrict__ bias1,
    float* __restrict__ C0, float* __restrict__ C1, int do_relu)
{
    extern __shared__ char smem[];
    const uint32_t sbase = s2u(smem);
    const int tid = threadIdx.x;
    const int dom = blockIdx.y;
    const int m0 = blockIdx.x * 128;

    const char* sA  = (const char*)(dom ? A1 : A0);
    const char* sBh = (const char*)g_Wth[dom ? wi1 : wi0];
    const char* sBl = (const char*)g_Wtl[dom ? wi1 : wi0];
    const float* __restrict__ bias = dom ? bias1 : bias0;
    float* __restrict__ C = dom ? C1 : C0;

    const int w   = tid >> 5;
    const int L   = tid & 31;
    const int wm0 = (w & 3) * 32;
    const int wn0 = (w >> 2) * 64;

    Frag F;
    #pragma unroll
    for (int i = 0; i < 2; i++)
        #pragma unroll
        for (int j = 0; j < 8; j++)
            #pragma unroll
            for (int q = 0; q < 4; q++) F.acc[i][j][q] = 0.f;

    auto copy_stage = [&](int stage, int kt) {
        const uint32_t st = sbase + (uint32_t)stage * STAGE_M;
        const size_t kbA = (size_t)kt * 128;
        #pragma unroll
        for (int q = 0; q < 4; ++q) {
            const int idx = q * 256 + tid;
            const int row = idx >> 3;
            const int c   = idx & 7;
            cp16(st + atile_off(row, c),
                 sA + (((size_t)(m0 + row)) << 9) + kbA + ((size_t)c << 4));
        }
        const size_t kbB = (size_t)kt * 64;
        #pragma unroll
        for (int q = 0; q < 4; ++q) {
            const int idx  = q * 256 + tid;
            const int tile = idx >> 9;
            const int rem  = idx & 511;
            const int row  = rem >> 2;
            const int c    = rem & 3;
            const char* gp = (tile ? sBl : sBh) + ((size_t)row << 8) + kbB
                             + ((size_t)c << 4);
            cp16(st + 16384u + (uint32_t)tile * 8192u + tile_off(row, c), gp);
        }
        asm volatile("cp.async.commit_group;" ::: "memory");
    };

    copy_stage(0, 0);
    copy_stage(1, 1);

    for (int kt = 0; kt < KTM; ++kt) {
        if (kt + 1 < KTM) asm volatile("cp.async.wait_group 1;" ::: "memory");
        else              asm volatile("cp.async.wait_group 0;" ::: "memory");
        __syncthreads();
        stage_mma3(F, sbase + (uint32_t)(kt % 3) * STAGE_M, wm0, wn0, L);
        if (kt + 2 < KTM) copy_stage((kt + 2) % 3, kt + 2);
    }

    #pragma unroll
    for (int mi = 0; mi < 2; ++mi) {
        const int r0 = m0 + wm0 + mi * 16 + (L >> 2);
        #pragma unroll
        for (int ni = 0; ni < 8; ++ni) {
            const int col = wn0 + ni * 8 + (L & 3) * 2;
            float b0 = bias[col], b1 = bias[col + 1];
            float v00 = F.acc[mi][ni][0] + b0, v01 = F.acc[mi][ni][1] + b1;
            float v10 = F.acc[mi][ni][2] + b0, v11 = F.acc[mi][ni][3] + b1;
            if (do_relu) {
                v00 = fmaxf(v00, 0.f); v01 = fmaxf(v01, 0.f);
                v10 = fmaxf(v10, 0.f); v11 = fmaxf(v11, 0.f);
            }
            *(float2*)&C[(size_t)r0 * DD + col]       = make_float2(v00, v01);
            *(float2*)&C[(size_t)(r0 + 8) * DD + col] = make_float2(v10, v11);
        }
    }
}

// ---------------- transpose: sum of nparts [4096,128] f32 -> [128,4096] fp16 ---
__global__ void __launch_bounds__(256) transpose_half(
    const float* __restrict__ s0, int nparts, __half* __restrict__ out)
{
    __shared__ float t[32][33];
    const int tx = threadIdx.x, ty = threadIdx.y;   // block (32, 8)
    #pragma unroll
    for (int j = 0; j < 4; ++j) {
        int r = blockIdx.x * 32 + ty + j * 8;
        int c = blockIdx.y * 32 + tx;
        float v = 0.f;
        for (int p = 0; p < nparts; ++p)
            v += s0[(size_t)p * NN * DD + (size_t)r * DD + c];
        t[ty + j * 8][tx] = v;
    }
    __syncthreads();
    #pragma unroll
    for (int j = 0; j < 4; ++j) {
        int oc = blockIdx.y * 32 + ty + j * 8;
        int orr = blockIdx.x * 32 + tx;
        out[(size_t)oc * NN + orr] = __float2half(t[tx][ty + j * 8]);
    }
}

// ---------------- MLP weight transpose+split (fp16 hi/lo) ----------------------
__global__ void __launch_bounds__(256) w_split(
    const float* __restrict__ w0, const float* __restrict__ w1,
    const float* __restrict__ w2, const float* __restrict__ w3)
{
    const float* W = (blockIdx.y == 0) ? w0 : (blockIdx.y == 1) ? w1
                     : (blockIdx.y == 2) ? w2 : w3;
    int idx = blockIdx.x * 256 + threadIdx.x;
    int k = idx >> 7, n = idx & 127;
    float v = W[idx];
    __half h = __float2half(v);
    g_Wth[blockIdx.y][n * DD + k] = h;
    g_Wtl[blockIdx.y][n * DD + k] = __float2half(v - __half2float(h));
}

// ---------------- review rowsums ------------------------------------------------
__global__ void __launch_bounds__(256) rowsum_kernel(
    const float* __restrict__ revA, const float* __restrict__ revB)
{
    const int dom = blockIdx.y;
    const float* __restrict__ rev = dom ? revB : revA;
    const int row = blockIdx.x * 8 + (threadIdx.x >> 5);
    const int lane = threadIdx.x & 31;
    const float4* p = (const float4*)(rev + (size_t)row * NN);
    float s = 0.f;
    #pragma unroll 4
    for (int j = lane; j < NN / 4; j += 32) {
        float4 v = p[j];
        s += (v.x + v.y) + (v.z + v.w);
    }
    #pragma unroll
    for (int o = 16; o; o >>= 1) s += __shfl_xor_sync(0xffffffffu, s, o);
    if (!lane) g_rowsum[dom][row] = s;
}

// ---------------- Wr colsums ----------------------------------------------------
__global__ void __launch_bounds__(1024) colsum_kernel(
    const float* __restrict__ WrA, const float* __restrict__ WrB)
{
    const int dom = blockIdx.x;
    const float* __restrict__ W = dom ? WrB : WrA;
    __shared__ float sm[8][128];
    const int d = threadIdx.x & 127;
    const int r = threadIdx.x >> 7;
    float s = 0.f;
    for (int k = r; k < NN; k += 8) s += W[k * DD + d];
    sm[r][d] = s;
    __syncthreads();
    if (r == 0) {
        float t = 0.f;
        #pragma unroll
        for (int q = 0; q < 8; q++) t += sm[q][d];
        g_colsum[dom][d] = t;
    }
}

// ---------------- gather + K-split combine + review rank-1 + attention ---------
__global__ void __launch_bounds__(256) gather_combine(
    const int* __restrict__ u, const int* __restrict__ iidx,
    const int* __restrict__ domain_p,
    const float* __restrict__ att_A, const float* __restrict__ att_B)
{
    const int idx = blockIdx.x * 256 + threadIdx.x;
    const int b = idx >> 7, d = idx & 127;
    const int dom = domain_p ? domain_p[0] : 0;
    const int uu = u[b], ii = iidx[b];

    const size_t ud = (size_t)uu * DD + d;
    float sA_ = 0.f, sB_ = 0.f;
    #pragma unroll
    for (int z = 0; z < KSPLIT; ++z) {
        sA_ += g_Cpart[z][ud];
        sB_ += g_Cpart[KSPLIT + z][ud];
    }
    float uA = fmaxf(sA_, 0.f) + fmaxf(g_rowsum[0][uu] * g_colsum[0][d], 0.f);
    float uB = fmaxf(sB_, 0.f) + fmaxf(g_rowsum[1][uu] * g_colsum[1][d], 0.f);

    const size_t id_ = (size_t)ii * DD + d;
    float it = 0.f;
    #pragma unroll
    for (int z = 0; z < KSPLIT; ++z)
        it += g_Cpart[(dom ? KSPLIT : 0) + z][id_];

    float user;
    if (dom == 0) {
        float w = att_A[uu * DD + d];
        user = uA * w + uB * (1.f - w);
    } else {
        float w = att_B[uu * DD + d];
        user = uB * w + uA * (1.f - w);
    }
    g_pre[0][idx] = user;
    g_pre[1][idx] = fmaxf(it, 0.f);
}

// ---------------- launch --------------------------------------------------------
extern "C" void kernel_launch(void* const* d_in, const int* in_sizes, int n_in,
                              void* d_out, int out_size)
{
    const float* rating_A = (const float*)d_in[0];
    const float* rating_B = (const float*)d_in[1];
    const float* review_A = (const float*)d_in[2];
    const float* review_B = (const float*)d_in[3];
    const float* Wg_A = (const float*)d_in[4];
    const float* Wg_B = (const float*)d_in[5];
    const float* Wr_A = (const float*)d_in[6];
    const float* Wr_B = (const float*)d_in[7];
    const float* att_A = (const float*)d_in[8];
    const float* att_B = (const float*)d_in[9];
    const float* uW1 = (const float*)d_in[10];
    const float* ub1 = (const float*)d_in[11];
    const float* uW2 = (const float*)d_in[12];
    const float* ub2 = (const float*)d_in[13];
    const float* iW1 = (const float*)d_in[14];
    const float* ib1 = (const float*)d_in[15];
    const float* iW2 = (const float*)d_in[16];
    const float* ib2 = (const float*)d_in[17];
    const int*   u_idx = (const int*)d_in[18];
    const int*   i_idx = (const int*)d_in[19];
    const int*   domain = (n_in > 20) ? (const int*)d_in[20] : nullptr;

    float* out_user = (float*)d_out;
    float* out_item = (float*)d_out + (size_t)BB * DD;

    __half* Bt;
    float *Cp, *P0, *Hd0;
    cudaGetSymbolAddress((void**)&Bt, g_Bt);
    cudaGetSymbolAddress((void**)&Cp, g_Cpart);
    cudaGetSymbolAddress((void**)&P0, g_pre);
    cudaGetSymbolAddress((void**)&Hd0, g_hid);

    const size_t NBT = (size_t)DD * NN;
    const size_t NCD = (size_t)NN * DD;
    float* P1 = P0 + NCD;
    float* Hd1 = Hd0 + NCD;
    float* CpA = Cp;
    float* CpB = Cp + KSPLIT * NCD;

    // ---- one-time handle creation on the first (uncaptured) call -------------
    static cudaStream_t sB = nullptr, sC = nullptr;
    static cudaEvent_t evFork = nullptr, evB = nullptr, evC = nullptr;
    if (sB == nullptr) {
        cudaStreamCreateWithFlags(&sB, cudaStreamNonBlocking);
        cudaStreamCreateWithFlags(&sC, cudaStreamNonBlocking);
        cudaEventCreateWithFlags(&evFork, cudaEventDisableTiming);
        cudaEventCreateWithFlags(&evB,    cudaEventDisableTiming);
        cudaEventCreateWithFlags(&evC,    cudaEventDisableTiming);
        cudaFuncSetAttribute(tc_gemm, cudaFuncAttributeMaxDynamicSharedMemorySize, TCG_SMEM_G);
        cudaFuncSetAttribute(tc_mlp,  cudaFuncAttributeMaxDynamicSharedMemorySize, TCG_SMEM_M);
        // pre-warm streams/events so lazy driver allocations land pre-baseline
        cudaEventRecord(evFork, MAIN_S);
        cudaStreamWaitEvent(sB, evFork, 0);
        cudaStreamWaitEvent(sC, evFork, 0);
        cudaEventRecord(evB, sB);
        cudaEventRecord(evC, sC);
        cudaStreamWaitEvent(MAIN_S, evB, 0);
        cudaStreamWaitEvent(MAIN_S, evC, 0);
    }

    dim3 blk(256);
    dim3 tsg(NN / 32, DD / 32), tsb(32, 8);
    dim3 gemm_grid(NN / 128, 1, KSPLIT);

    cudaEventRecord(evFork, MAIN_S);
    cudaStreamWaitEvent(sB, evFork, 0);
    cudaStreamWaitEvent(sC, evFork, 0);

    // ---- domain A chain (MAIN_S) ----
    transpose_half<<<tsg, tsb, 0, MAIN_S>>>(Wg_A, 1, Bt);
    tc_gemm<<<gemm_grid, blk, TCG_SMEM_G, MAIN_S>>>(rating_A, Bt, CpA);
    transpose_half<<<tsg, tsb, 0, MAIN_S>>>(CpA, KSPLIT, Bt);
    tc_gemm<<<gemm_grid, blk, TCG_SMEM_G, MAIN_S>>>(rating_A, Bt, CpA);

    // ---- domain B chain (sB) ----
    transpose_half<<<tsg, tsb, 0, sB>>>(Wg_B, 1, Bt + NBT);
    tc_gemm<<<gemm_grid, blk, TCG_SMEM_G, sB>>>(rating_B, Bt + NBT, CpB);
    transpose_half<<<tsg, tsb, 0, sB>>>(CpB, KSPLIT, Bt + NBT);
    tc_gemm<<<gemm_grid, blk, TCG_SMEM_G, sB>>>(rating_B, Bt + NBT, CpB);
    cudaEventRecord(evB, sB);

    // ---- side work (sC) ----
    rowsum_kernel<<<dim3(NN / 8, 2), blk, 0, sC>>>(review_A, review_B);
    colsum_kernel<<<dim3(2), dim3(1024), 0, sC>>>(Wr_A, Wr_B);
    w_split<<<dim3(64, 4), blk, 0, sC>>>(uW1, iW1, uW2, iW2);
    cudaEventRecord(evC, sC);

    // ---- join, then gather + MLPs on MAIN_S ----
    cudaStreamWaitEvent(MAIN_S, evB, 0);
    cudaStreamWaitEvent(MAIN_S, evC, 0);

    gather_combine<<<dim3((BB * DD) / 256), blk, 0, MAIN_S>>>(u_idx, i_idx, domain,
                                                              att_A, att_B);
    tc_mlp<<<dim3(BB / 128, 2), blk, TCG_SMEM_M, MAIN_S>>>(
        P0, P1, 0, 1, ub1, ib1, Hd0, Hd1, 1);
    tc_mlp<<<dim3(BB / 128, 2), blk, TCG_SMEM_M, MAIN_S>>>(
        Hd0, Hd1, 2, 3, ub2, ib2, out_user, out_item, 0);
}